// round 11
// baseline (speedup 1.0000x reference)
#include <cuda_runtime.h>
#include <cstdint>

#define B_  2
#define S_  2048
#define D_  1024
#define H_  16
#define DH_ 64
#define M_  (B_*S_)

// Scratch for projected Q/K/V (allocation-free rule: __device__ globals)
__device__ float g_Q[M_*D_];
__device__ float g_K[M_*D_];
__device__ float g_V[M_*D_];

// ---------------------------------------------------------------------------
// Helpers (family-level PTX only — compute_103 has no tcgen05)
// ---------------------------------------------------------------------------
__device__ __forceinline__ uint32_t smem_u32(const void* p){
    uint32_t a;
    asm("{ .reg .u64 t; cvta.to.shared.u64 t, %1; cvt.u32.u64 %0, t; }"
        : "=r"(a) : "l"(p));
    return a;
}
__device__ __forceinline__ float to_tf32(float x){
    asm("cvt.rna.tf32.f32 %0, %0;" : "+f"(x));
    return x;
}
__device__ __forceinline__ void cp16(uint32_t dst, const void* src){
    asm volatile("cp.async.cg.shared.global [%0], [%1], 16;"
                 :: "r"(dst), "l"(src) : "memory");
}
__device__ __forceinline__ void cp_commit(){
    asm volatile("cp.async.commit_group;" ::: "memory");
}
__device__ __forceinline__ void cp_wait0(){
    asm volatile("cp.async.wait_group 0;" ::: "memory");
}
__device__ __forceinline__ void cp_wait1(){
    asm volatile("cp.async.wait_group 1;" ::: "memory");
}
// m16n8k8 tf32 mma (sm_80+): D = A*B + D
__device__ __forceinline__ void mma_tf32(float* c, const float* a, const float* b){
    asm volatile(
        "mma.sync.aligned.m16n8k8.row.col.f32.tf32.tf32.f32 "
        "{%0,%1,%2,%3}, {%4,%5,%6,%7}, {%8,%9}, {%0,%1,%2,%3};"
        : "+f"(c[0]), "+f"(c[1]), "+f"(c[2]), "+f"(c[3])
        : "r"(__float_as_uint(a[0])), "r"(__float_as_uint(a[1])),
          "r"(__float_as_uint(a[2])), "r"(__float_as_uint(a[3])),
          "r"(__float_as_uint(b[0])), "r"(__float_as_uint(b[1])));
}

// ---------------------------------------------------------------------------
// Projection GEMM via mma.sync tf32 (unchanged — passing since R7)
// ---------------------------------------------------------------------------
#define AST 36
#define BST 136
#define PA_FLOATS (128*AST)
#define PB_FLOATS (32*BST)
#define PBUF_FLOATS (PA_FLOATS + PB_FLOATS)
#define PA_BYTES (PA_FLOATS*4)
#define PBUF_BYTES (PBUF_FLOATS*4)
#define PSMEM_TOT (2*PBUF_BYTES)

__global__ __launch_bounds__(256, 2)
void proj_mma(const float* __restrict__ Aq, const float* __restrict__ Ak,
              const float* __restrict__ Av,
              const float* __restrict__ Wq, const float* __restrict__ Wk,
              const float* __restrict__ Wv,
              const float* __restrict__ bq, const float* __restrict__ bk,
              const float* __restrict__ bv)
{
    extern __shared__ float sm[];
    const uint32_t smb = smem_u32(sm);
    const int tid  = threadIdx.x;
    const int wid  = tid >> 5;
    const int lane = tid & 31;
    const int wm   = wid >> 2;
    const int wn   = wid & 3;
    const int grp  = lane >> 2;
    const int qd   = lane & 3;

    const int z = blockIdx.z;
    const float* A    = (z == 0) ? Aq : (z == 1) ? Ak : Av;
    const float* W    = (z == 0) ? Wq : (z == 1) ? Wk : Wv;
    const float* bias = (z == 0) ? bq : (z == 1) ? bk : bv;
    float* C          = (z == 0) ? g_Q : (z == 1) ? g_K : g_V;
    const int brow = blockIdx.y * 128;
    const int bcol = blockIdx.x * 128;

    auto cp_chunk = [&](int c, int buf){
        const int k0 = c * 32;
        const uint32_t Ab = smb + buf * PBUF_BYTES;
        const uint32_t Bb = Ab + PA_BYTES;
        #pragma unroll
        for (int it = 0; it < 4; it++) {
            int idx = tid + it * 256;
            int row = idx >> 3;
            int k4  = idx & 7;
            cp16(Ab + row * (AST*4) + k4 * 16,
                 &A[(size_t)(brow + row) * D_ + k0 + k4 * 4]);
        }
        #pragma unroll
        for (int it = 0; it < 4; it++) {
            int idx = tid + it * 256;
            int kk  = idx >> 5;
            int n4  = idx & 31;
            cp16(Bb + kk * (BST*4) + n4 * 16,
                 &W[(size_t)(k0 + kk) * D_ + bcol + n4 * 4]);
        }
    };

    float acc[4][4][4];
    #pragma unroll
    for (int i = 0; i < 4; i++)
        #pragma unroll
        for (int j = 0; j < 4; j++)
            #pragma unroll
            for (int r = 0; r < 4; r++) acc[i][j][r] = 0.f;

    cp_chunk(0, 0);
    cp_commit();
    cp_wait0();
    __syncthreads();

    for (int c = 0; c < 32; c++) {
        const int buf = c & 1;
        const float* A_s = sm + buf * PBUF_FLOATS;
        const float* B_s = A_s + PA_FLOATS;

        if (c + 1 < 32) { cp_chunk(c + 1, buf ^ 1); cp_commit(); }

        #pragma unroll
        for (int ks = 0; ks < 4; ks++) {
            float a[4][4];
            #pragma unroll
            for (int i = 0; i < 4; i++) {
                const int r0 = wm * 64 + i * 16 + grp;
                const float* Ar = &A_s[r0 * AST + ks * 8 + qd];
                a[i][0] = to_tf32(Ar[0]);
                a[i][1] = to_tf32(Ar[8 * AST]);
                a[i][2] = to_tf32(Ar[4]);
                a[i][3] = to_tf32(Ar[8 * AST + 4]);
            }
            float bf[4][2];
            #pragma unroll
            for (int j = 0; j < 4; j++) {
                const int col = wn * 32 + j * 8 + grp;
                bf[j][0] = to_tf32(B_s[(ks * 8 + qd) * BST + col]);
                bf[j][1] = to_tf32(B_s[(ks * 8 + qd + 4) * BST + col]);
            }
            #pragma unroll
            for (int i = 0; i < 4; i++)
                #pragma unroll
                for (int j = 0; j < 4; j++)
                    mma_tf32(acc[i][j], a[i], bf[j]);
        }

        if (c + 1 < 32) cp_wait0();
        __syncthreads();
    }

    #pragma unroll
    for (int j = 0; j < 4; j++) {
        const int c0 = bcol + wn * 32 + j * 8 + qd * 2;
        const float2 bb = *(const float2*)&bias[c0];
        #pragma unroll
        for (int i = 0; i < 4; i++) {
            const int r0 = brow + wm * 64 + i * 16 + grp;
            float2 o0 = make_float2(acc[i][j][0] + bb.x, acc[i][j][1] + bb.y);
            float2 o1 = make_float2(acc[i][j][2] + bb.x, acc[i][j][3] + bb.y);
            *(float2*)&C[(size_t)r0 * D_ + c0]       = o0;
            *(float2*)&C[(size_t)(r0 + 8) * D_ + c0] = o1;
        }
    }
}

// ---------------------------------------------------------------------------
// Flash attention v2: 256 thr (8 warps x 16 q-rows), BM=128, kv tiles of 64.
// Q fragments register-resident (staged via P region). K/V cp.async
// double-buffered raw fp32; cvt.rna at fragment load. 2 barriers/tile.
// K/P stride 68 (banks 4*grp+qd), V stride 72 (banks 8*qd+grp): conflict-free.
// ---------------------------------------------------------------------------
#define KST 68
#define VST 72
#define PST 68
#define OFF_K 0
#define OFF_V (2*64*KST)
#define OFF_P (OFF_V + 2*64*VST)
#define OFF_M (OFF_P + 128*PST)
#define FA_FLOATS (OFF_M + 64)
#define FA_BYTES (FA_FLOATS * 4)        // 106752 B -> 2 CTAs/SM

__global__ __launch_bounds__(256, 2)
void flash_attn_mma(const int* __restrict__ mask, float* __restrict__ out)
{
    extern __shared__ float smf[];
    float* Ks   = smf + OFF_K;          // [2][64][KST] raw fp32
    float* Vs   = smf + OFF_V;          // [2][64][VST] raw fp32
    float* Ps   = smf + OFF_P;          // [128][PST] tf32 (warp-private rows)
    float* madd = smf + OFF_M;          // [64]
    const uint32_t smb = smem_u32(smf);

    const int tid  = threadIdx.x;
    const int w    = tid >> 5;          // 0..7 -> q rows [w*16, w*16+16)
    const int lane = tid & 31;
    const int grp  = lane >> 2;
    const int qd   = lane & 3;
    const int bh   = blockIdx.y;
    const int b    = bh >> 4;
    const int h    = bh & 15;
    const int q0   = blockIdx.x * 128;
    const float scale = 0.03125f;       // 1/sqrt(1024)

    const float* Qb = g_Q + (size_t)b * S_ * D_ + h * DH_;
    const float* Kb = g_K + (size_t)b * S_ * D_ + h * DH_;
    const float* Vb = g_V + (size_t)b * S_ * D_ + h * DH_;

    auto cp_tile = [&](int it, int buf){
        const int kv0 = it * 64;
        const uint32_t Kd = smb + (OFF_K + buf * 64 * KST) * 4;
        const uint32_t Vd = smb + (OFF_V + buf * 64 * VST) * 4;
        #pragma unroll
        for (int l = 0; l < 4; l++) {
            int idx = tid + l * 256;        // 0..1023 float4s
            int row = idx >> 4;
            int c4  = idx & 15;
            cp16(Kd + (row * KST + c4 * 4) * 4,
                 &Kb[(size_t)(kv0 + row) * D_ + c4 * 4]);
            cp16(Vd + (row * VST + c4 * 4) * 4,
                 &Vb[(size_t)(kv0 + row) * D_ + c4 * 4]);
        }
    };

    // Prefetch kv tiles 0 and 1 while we stage Q
    cp_tile(0, 0); cp_commit();
    cp_tile(1, 1); cp_commit();

    // Stage this warp's 16 Q rows through its private P region -> registers
    #pragma unroll
    for (int l = 0; l < 8; l++) {
        int idx = lane + l * 32;            // 0..255 float4s
        int row = idx >> 4;
        int c4  = idx & 15;
        float4 v = *(const float4*)&Qb[(size_t)(q0 + w * 16 + row) * D_ + c4 * 4];
        v.x = to_tf32(v.x); v.y = to_tf32(v.y);
        v.z = to_tf32(v.z); v.w = to_tf32(v.w);
        *(float4*)&Ps[(w * 16 + row) * PST + c4 * 4] = v;
    }
    __syncwarp();
    const int rl = w * 16 + grp;            // fragment row (and rl+8)
    float q[8][4];
    #pragma unroll
    for (int kt = 0; kt < 8; kt++) {
        q[kt][0] = Ps[rl * PST + kt * 8 + qd];
        q[kt][1] = Ps[(rl + 8) * PST + kt * 8 + qd];
        q[kt][2] = Ps[rl * PST + kt * 8 + qd + 4];
        q[kt][3] = Ps[(rl + 8) * PST + kt * 8 + qd + 4];
    }

    int mreg = 0;
    if (tid < 64) mreg = mask[b * S_ + tid];

    float o[8][4];
    #pragma unroll
    for (int nt = 0; nt < 8; nt++)
        #pragma unroll
        for (int r = 0; r < 4; r++) o[nt][r] = 0.f;
    float m0 = -1e30f, m1 = -1e30f, l0 = 0.f, l1 = 0.f;

    for (int it = 0; it < 32; it++) {
        const int buf = it & 1;
        if (it < 31) cp_wait1(); else cp_wait0();
        if (tid < 64) madd[tid] = mreg ? 0.f : -1e9f;
        __syncthreads();                    // K/V tile + madd visible
        if (it + 1 < 32 && tid < 64)
            mreg = mask[b * S_ + (it + 1) * 64 + tid];   // prefetch

        const float* Kc = Ks + buf * 64 * KST;
        const float* Vc = Vs + buf * 64 * VST;

        // ---- S = Q K^T (cvt at fragment load) ---------------------------
        float s[8][4];
        #pragma unroll
        for (int nt = 0; nt < 8; nt++)
            #pragma unroll
            for (int r = 0; r < 4; r++) s[nt][r] = 0.f;

        #pragma unroll
        for (int kt = 0; kt < 8; kt++) {
            #pragma unroll
            for (int nt = 0; nt < 8; nt++) {
                float bk[2];
                bk[0] = to_tf32(Kc[(nt * 8 + grp) * KST + kt * 8 + qd]);
                bk[1] = to_tf32(Kc[(nt * 8 + grp) * KST + kt * 8 + qd + 4]);
                mma_tf32(s[nt], q[kt], bk);
            }
        }

        // ---- online softmax ---------------------------------------------
        float mx0 = -1e30f, mx1 = -1e30f;
        #pragma unroll
        for (int nt = 0; nt < 8; nt++) {
            float2 ma = *(float2*)&madd[nt * 8 + 2 * qd];
            s[nt][0] = fmaf(s[nt][0], scale, ma.x);
            s[nt][1] = fmaf(s[nt][1], scale, ma.y);
            s[nt][2] = fmaf(s[nt][2], scale, ma.x);
            s[nt][3] = fmaf(s[nt][3], scale, ma.y);
            mx0 = fmaxf(mx0, fmaxf(s[nt][0], s[nt][1]));
            mx1 = fmaxf(mx1, fmaxf(s[nt][2], s[nt][3]));
        }
        mx0 = fmaxf(mx0, __shfl_xor_sync(0xffffffffu, mx0, 1));
        mx0 = fmaxf(mx0, __shfl_xor_sync(0xffffffffu, mx0, 2));
        mx1 = fmaxf(mx1, __shfl_xor_sync(0xffffffffu, mx1, 1));
        mx1 = fmaxf(mx1, __shfl_xor_sync(0xffffffffu, mx1, 2));
        const float mn0 = fmaxf(m0, mx0);
        const float mn1 = fmaxf(m1, mx1);
        const float al0 = __expf(m0 - mn0);
        const float al1 = __expf(m1 - mn1);
        float rs0 = 0.f, rs1 = 0.f;
        #pragma unroll
        for (int nt = 0; nt < 8; nt++) {
            float p0 = __expf(s[nt][0] - mn0);
            float p1 = __expf(s[nt][1] - mn0);
            float p2 = __expf(s[nt][2] - mn1);
            float p3 = __expf(s[nt][3] - mn1);
            rs0 += p0 + p1;
            rs1 += p2 + p3;
            *(float2*)&Ps[rl * PST + nt * 8 + 2 * qd] =
                make_float2(to_tf32(p0), to_tf32(p1));
            *(float2*)&Ps[(rl + 8) * PST + nt * 8 + 2 * qd] =
                make_float2(to_tf32(p2), to_tf32(p3));
        }
        rs0 += __shfl_xor_sync(0xffffffffu, rs0, 1);
        rs0 += __shfl_xor_sync(0xffffffffu, rs0, 2);
        rs1 += __shfl_xor_sync(0xffffffffu, rs1, 1);
        rs1 += __shfl_xor_sync(0xffffffffu, rs1, 2);
        l0 = l0 * al0 + rs0;
        l1 = l1 * al1 + rs1;
        m0 = mn0;
        m1 = mn1;
        #pragma unroll
        for (int nt = 0; nt < 8; nt++) {
            o[nt][0] *= al0; o[nt][1] *= al0;
            o[nt][2] *= al1; o[nt][3] *= al1;
        }
        __syncwarp();   // P rows are warp-private

        // ---- O += P V (cvt V at fragment load) --------------------------
        #pragma unroll
        for (int kt = 0; kt < 8; kt++) {
            float a[4];
            a[0] = Ps[rl * PST + kt * 8 + qd];
            a[1] = Ps[(rl + 8) * PST + kt * 8 + qd];
            a[2] = Ps[rl * PST + kt * 8 + qd + 4];
            a[3] = Ps[(rl + 8) * PST + kt * 8 + qd + 4];
            #pragma unroll
            for (int nt = 0; nt < 8; nt++) {
                float bv[2];
                bv[0] = to_tf32(Vc[(kt * 8 + qd) * VST + nt * 8 + grp]);
                bv[1] = to_tf32(Vc[(kt * 8 + qd + 4) * VST + nt * 8 + grp]);
                mma_tf32(o[nt], a, bv);
            }
        }
        __syncthreads();                    // all warps done with this buf
        if (it + 2 < 32) { cp_tile(it + 2, buf); cp_commit(); }
    }

    // ---- normalize + write ----------------------------------------------
    const float inv0 = 1.f / l0;
    const float inv1 = 1.f / l1;
    #pragma unroll
    for (int nt = 0; nt < 8; nt++) {
        const int col = h * DH_ + nt * 8 + 2 * qd;
        *(float2*)&out[((size_t)b * S_ + q0 + rl) * D_ + col] =
            make_float2(o[nt][0] * inv0, o[nt][1] * inv0);
        *(float2*)&out[((size_t)b * S_ + q0 + rl + 8) * D_ + col] =
            make_float2(o[nt][2] * inv1, o[nt][3] * inv1);
    }
}

// ---------------------------------------------------------------------------
extern "C" void kernel_launch(void* const* d_in, const int* in_sizes, int n_in,
                              void* d_out, int out_size)
{
    const float* q    = (const float*)d_in[0];
    const float* k    = (const float*)d_in[1];
    const float* v    = (const float*)d_in[2];
    const int*   mask = (const int*)  d_in[3];
    const float* Wq   = (const float*)d_in[4];
    const float* bq   = (const float*)d_in[5];
    const float* Wk   = (const float*)d_in[6];
    const float* bk   = (const float*)d_in[7];
    const float* Wv   = (const float*)d_in[8];
    const float* bv   = (const float*)d_in[9];
    float* out = (float*)d_out;

    (void)in_sizes; (void)n_in; (void)out_size;

    cudaFuncSetAttribute(proj_mma,
                         cudaFuncAttributeMaxDynamicSharedMemorySize, PSMEM_TOT);
    dim3 g1(D_/128, M_/128, 3);
    proj_mma<<<g1, 256, PSMEM_TOT>>>(q, k, v, Wq, Wk, Wv, bq, bk, bv);

    cudaFuncSetAttribute(flash_attn_mma,
                         cudaFuncAttributeMaxDynamicSharedMemorySize, FA_BYTES);
    dim3 g2(S_/128, B_*H_);
    flash_attn_mma<<<g2, 256, FA_BYTES>>>(mask, out);
}

// round 12
// speedup vs baseline: 1.0710x; 1.0710x over previous
#include <cuda_runtime.h>
#include <cstdint>

#define B_  2
#define S_  2048
#define D_  1024
#define H_  16
#define DH_ 64
#define M_  (B_*S_)

// Scratch for projected Q/K/V (allocation-free rule: __device__ globals)
__device__ float g_Q[M_*D_];
__device__ float g_K[M_*D_];
__device__ float g_V[M_*D_];

// ---------------------------------------------------------------------------
// Helpers (family-level PTX only — compute_103 has no tcgen05)
// ---------------------------------------------------------------------------
__device__ __forceinline__ uint32_t smem_u32(const void* p){
    uint32_t a;
    asm("{ .reg .u64 t; cvta.to.shared.u64 t, %1; cvt.u32.u64 %0, t; }"
        : "=r"(a) : "l"(p));
    return a;
}
__device__ __forceinline__ float to_tf32(float x){
    asm("cvt.rna.tf32.f32 %0, %0;" : "+f"(x));
    return x;
}
__device__ __forceinline__ void cp16(uint32_t dst, const void* src){
    asm volatile("cp.async.cg.shared.global [%0], [%1], 16;"
                 :: "r"(dst), "l"(src) : "memory");
}
__device__ __forceinline__ void cp_commit(){
    asm volatile("cp.async.commit_group;" ::: "memory");
}
__device__ __forceinline__ void cp_wait0(){
    asm volatile("cp.async.wait_group 0;" ::: "memory");
}
__device__ __forceinline__ void cp_wait1(){
    asm volatile("cp.async.wait_group 1;" ::: "memory");
}
// m16n8k8 tf32 mma (sm_80+): D = A*B + D
__device__ __forceinline__ void mma_tf32(float* c, const float* a, const float* b){
    asm volatile(
        "mma.sync.aligned.m16n8k8.row.col.f32.tf32.tf32.f32 "
        "{%0,%1,%2,%3}, {%4,%5,%6,%7}, {%8,%9}, {%0,%1,%2,%3};"
        : "+f"(c[0]), "+f"(c[1]), "+f"(c[2]), "+f"(c[3])
        : "r"(__float_as_uint(a[0])), "r"(__float_as_uint(a[1])),
          "r"(__float_as_uint(a[2])), "r"(__float_as_uint(a[3])),
          "r"(__float_as_uint(b[0])), "r"(__float_as_uint(b[1])));
}

// ---------------------------------------------------------------------------
// Projection GEMM via mma.sync tf32 (unchanged — passing since R7)
// ---------------------------------------------------------------------------
#define AST 36
#define BST 136
#define PA_FLOATS (128*AST)
#define PB_FLOATS (32*BST)
#define PBUF_FLOATS (PA_FLOATS + PB_FLOATS)
#define PA_BYTES (PA_FLOATS*4)
#define PBUF_BYTES (PBUF_FLOATS*4)
#define PSMEM_TOT (2*PBUF_BYTES)

__global__ __launch_bounds__(256, 2)
void proj_mma(const float* __restrict__ Aq, const float* __restrict__ Ak,
              const float* __restrict__ Av,
              const float* __restrict__ Wq, const float* __restrict__ Wk,
              const float* __restrict__ Wv,
              const float* __restrict__ bq, const float* __restrict__ bk,
              const float* __restrict__ bv)
{
    extern __shared__ float sm[];
    const uint32_t smb = smem_u32(sm);
    const int tid  = threadIdx.x;
    const int wid  = tid >> 5;
    const int lane = tid & 31;
    const int wm   = wid >> 2;
    const int wn   = wid & 3;
    const int grp  = lane >> 2;
    const int qd   = lane & 3;

    const int z = blockIdx.z;
    const float* A    = (z == 0) ? Aq : (z == 1) ? Ak : Av;
    const float* W    = (z == 0) ? Wq : (z == 1) ? Wk : Wv;
    const float* bias = (z == 0) ? bq : (z == 1) ? bk : bv;
    float* C          = (z == 0) ? g_Q : (z == 1) ? g_K : g_V;
    const int brow = blockIdx.y * 128;
    const int bcol = blockIdx.x * 128;

    auto cp_chunk = [&](int c, int buf){
        const int k0 = c * 32;
        const uint32_t Ab = smb + buf * PBUF_BYTES;
        const uint32_t Bb = Ab + PA_BYTES;
        #pragma unroll
        for (int it = 0; it < 4; it++) {
            int idx = tid + it * 256;
            int row = idx >> 3;
            int k4  = idx & 7;
            cp16(Ab + row * (AST*4) + k4 * 16,
                 &A[(size_t)(brow + row) * D_ + k0 + k4 * 4]);
        }
        #pragma unroll
        for (int it = 0; it < 4; it++) {
            int idx = tid + it * 256;
            int kk  = idx >> 5;
            int n4  = idx & 31;
            cp16(Bb + kk * (BST*4) + n4 * 16,
                 &W[(size_t)(k0 + kk) * D_ + bcol + n4 * 4]);
        }
    };

    float acc[4][4][4];
    #pragma unroll
    for (int i = 0; i < 4; i++)
        #pragma unroll
        for (int j = 0; j < 4; j++)
            #pragma unroll
            for (int r = 0; r < 4; r++) acc[i][j][r] = 0.f;

    cp_chunk(0, 0);
    cp_commit();
    cp_wait0();
    __syncthreads();

    for (int c = 0; c < 32; c++) {
        const int buf = c & 1;
        const float* A_s = sm + buf * PBUF_FLOATS;
        const float* B_s = A_s + PA_FLOATS;

        if (c + 1 < 32) { cp_chunk(c + 1, buf ^ 1); cp_commit(); }

        #pragma unroll
        for (int ks = 0; ks < 4; ks++) {
            float a[4][4];
            #pragma unroll
            for (int i = 0; i < 4; i++) {
                const int r0 = wm * 64 + i * 16 + grp;
                const float* Ar = &A_s[r0 * AST + ks * 8 + qd];
                a[i][0] = to_tf32(Ar[0]);
                a[i][1] = to_tf32(Ar[8 * AST]);
                a[i][2] = to_tf32(Ar[4]);
                a[i][3] = to_tf32(Ar[8 * AST + 4]);
            }
            float bf[4][2];
            #pragma unroll
            for (int j = 0; j < 4; j++) {
                const int col = wn * 32 + j * 8 + grp;
                bf[j][0] = to_tf32(B_s[(ks * 8 + qd) * BST + col]);
                bf[j][1] = to_tf32(B_s[(ks * 8 + qd + 4) * BST + col]);
            }
            #pragma unroll
            for (int i = 0; i < 4; i++)
                #pragma unroll
                for (int j = 0; j < 4; j++)
                    mma_tf32(acc[i][j], a[i], bf[j]);
        }

        if (c + 1 < 32) cp_wait0();
        __syncthreads();
    }

    #pragma unroll
    for (int j = 0; j < 4; j++) {
        const int c0 = bcol + wn * 32 + j * 8 + qd * 2;
        const float2 bb = *(const float2*)&bias[c0];
        #pragma unroll
        for (int i = 0; i < 4; i++) {
            const int r0 = brow + wm * 64 + i * 16 + grp;
            float2 o0 = make_float2(acc[i][j][0] + bb.x, acc[i][j][1] + bb.y);
            float2 o1 = make_float2(acc[i][j][2] + bb.x, acc[i][j][3] + bb.y);
            *(float2*)&C[(size_t)r0 * D_ + c0]       = o0;
            *(float2*)&C[(size_t)(r0 + 8) * D_ + c0] = o1;
        }
    }
}

// ---------------------------------------------------------------------------
// Flash attention v3: 256 thr (8 warps x 16 q-rows), kv tiles of 64.
// Q fragments register-resident. K/V cp.async double-buffered raw fp32;
// per-tile IN-PLACE repack to dense fragment-major tf32 (warp w owns kt=w):
//   KF[(kt*8+nt)*64 + lane*2] = { K[nt*8+grp][kt*8+qd], K[..][kt*8+qd+4] }
//   VF[(kt*8+nt)*64 + lane*2] = { V[kt*8+qd][nt*8+grp], V[kt*8+qd+4][..] }
// MMA fragment loads become consecutive LDS64 (conflict-free), cvt once/elem.
// ---------------------------------------------------------------------------
#define KST 68
#define VST 72
#define PST 68
#define OFF_K 0
#define OFF_V (2*64*KST)
#define OFF_P (OFF_V + 2*64*VST)
#define OFF_M (OFF_P + 128*PST)
#define FA_FLOATS (OFF_M + 64)
#define FA_BYTES (FA_FLOATS * 4)        // 106752 B -> 2 CTAs/SM

__global__ __launch_bounds__(256, 2)
void flash_attn_mma(const int* __restrict__ mask, float* __restrict__ out)
{
    extern __shared__ float smf[];
    float* Ks   = smf + OFF_K;          // [2][64][KST] raw fp32 / then KF
    float* Vs   = smf + OFF_V;          // [2][64][VST] raw fp32 / then VF
    float* Ps   = smf + OFF_P;          // [128][PST] tf32 (warp-private rows)
    float* madd = smf + OFF_M;          // [64]
    const uint32_t smb = smem_u32(smf);

    const int tid  = threadIdx.x;
    const int w    = tid >> 5;          // 0..7 -> q rows [w*16, w*16+16)
    const int lane = tid & 31;
    const int grp  = lane >> 2;
    const int qd   = lane & 3;
    const int bh   = blockIdx.y;
    const int b    = bh >> 4;
    const int h    = bh & 15;
    const int q0   = blockIdx.x * 128;
    const float scale = 0.03125f;       // 1/sqrt(1024)

    const float* Qb = g_Q + (size_t)b * S_ * D_ + h * DH_;
    const float* Kb = g_K + (size_t)b * S_ * D_ + h * DH_;
    const float* Vb = g_V + (size_t)b * S_ * D_ + h * DH_;

    auto cp_tile = [&](int it, int buf){
        const int kv0 = it * 64;
        const uint32_t Kd = smb + (OFF_K + buf * 64 * KST) * 4;
        const uint32_t Vd = smb + (OFF_V + buf * 64 * VST) * 4;
        #pragma unroll
        for (int l = 0; l < 4; l++) {
            int idx = tid + l * 256;        // 0..1023 float4s
            int row = idx >> 4;
            int c4  = idx & 15;
            cp16(Kd + (row * KST + c4 * 4) * 4,
                 &Kb[(size_t)(kv0 + row) * D_ + c4 * 4]);
            cp16(Vd + (row * VST + c4 * 4) * 4,
                 &Vb[(size_t)(kv0 + row) * D_ + c4 * 4]);
        }
    };

    // Prefetch kv tiles 0 and 1 while we stage Q
    cp_tile(0, 0); cp_commit();
    cp_tile(1, 1); cp_commit();

    // Stage this warp's 16 Q rows through its private P region -> registers
    #pragma unroll
    for (int l = 0; l < 8; l++) {
        int idx = lane + l * 32;            // 0..255 float4s
        int row = idx >> 4;
        int c4  = idx & 15;
        float4 v = *(const float4*)&Qb[(size_t)(q0 + w * 16 + row) * D_ + c4 * 4];
        v.x = to_tf32(v.x); v.y = to_tf32(v.y);
        v.z = to_tf32(v.z); v.w = to_tf32(v.w);
        *(float4*)&Ps[(w * 16 + row) * PST + c4 * 4] = v;
    }
    __syncwarp();
    const int rl = w * 16 + grp;            // fragment row (and rl+8)
    float q[8][4];
    #pragma unroll
    for (int kt = 0; kt < 8; kt++) {
        q[kt][0] = Ps[rl * PST + kt * 8 + qd];
        q[kt][1] = Ps[(rl + 8) * PST + kt * 8 + qd];
        q[kt][2] = Ps[rl * PST + kt * 8 + qd + 4];
        q[kt][3] = Ps[(rl + 8) * PST + kt * 8 + qd + 4];
    }

    int mreg = 0;
    if (tid < 64) mreg = mask[b * S_ + tid];

    float o[8][4];
    #pragma unroll
    for (int nt = 0; nt < 8; nt++)
        #pragma unroll
        for (int r = 0; r < 4; r++) o[nt][r] = 0.f;
    float m0 = -1e30f, m1 = -1e30f, l0 = 0.f, l1 = 0.f;

    for (int it = 0; it < 32; it++) {
        const int buf = it & 1;
        if (it < 31) cp_wait1(); else cp_wait0();
        __syncthreads();                    // raw K/V tile visible to all

        float* Kc = Ks + buf * 64 * KST;    // raw now; KF after repack
        float* Vc = Vs + buf * 64 * VST;

        // ---- repack pass: read raw fragments (cvt once) into registers --
        float kf[8][2], vf[8][2];
        #pragma unroll
        for (int nt = 0; nt < 8; nt++) {
            kf[nt][0] = to_tf32(Kc[(nt * 8 + grp) * KST + w * 8 + qd]);
            kf[nt][1] = to_tf32(Kc[(nt * 8 + grp) * KST + w * 8 + qd + 4]);
            vf[nt][0] = to_tf32(Vc[(w * 8 + qd) * VST + nt * 8 + grp]);
            vf[nt][1] = to_tf32(Vc[(w * 8 + qd + 4) * VST + nt * 8 + grp]);
        }
        if (tid < 64) madd[tid] = mreg ? 0.f : -1e9f;
        if (it + 1 < 32 && tid < 64)
            mreg = mask[b * S_ + (it + 1) * 64 + tid];   // prefetch mask
        __syncthreads();                    // all raw reads complete

        // ---- write back IN PLACE, dense fragment-major ------------------
        #pragma unroll
        for (int nt = 0; nt < 8; nt++) {
            *(float2*)&Kc[(w * 8 + nt) * 64 + lane * 2] =
                make_float2(kf[nt][0], kf[nt][1]);
            *(float2*)&Vc[(w * 8 + nt) * 64 + lane * 2] =
                make_float2(vf[nt][0], vf[nt][1]);
        }
        __syncthreads();                    // KF/VF visible

        // ---- S = Q K^T (fragment-major LDS64, no cvt) -------------------
        float s[8][4];
        #pragma unroll
        for (int nt = 0; nt < 8; nt++)
            #pragma unroll
            for (int r = 0; r < 4; r++) s[nt][r] = 0.f;

        #pragma unroll
        for (int kt = 0; kt < 8; kt++) {
            #pragma unroll
            for (int nt = 0; nt < 8; nt++) {
                float2 bk = *(float2*)&Kc[(kt * 8 + nt) * 64 + lane * 2];
                mma_tf32(s[nt], q[kt], &bk.x);
            }
        }

        // ---- online softmax ---------------------------------------------
        float mx0 = -1e30f, mx1 = -1e30f;
        #pragma unroll
        for (int nt = 0; nt < 8; nt++) {
            float2 ma = *(float2*)&madd[nt * 8 + 2 * qd];
            s[nt][0] = fmaf(s[nt][0], scale, ma.x);
            s[nt][1] = fmaf(s[nt][1], scale, ma.y);
            s[nt][2] = fmaf(s[nt][2], scale, ma.x);
            s[nt][3] = fmaf(s[nt][3], scale, ma.y);
            mx0 = fmaxf(mx0, fmaxf(s[nt][0], s[nt][1]));
            mx1 = fmaxf(mx1, fmaxf(s[nt][2], s[nt][3]));
        }
        mx0 = fmaxf(mx0, __shfl_xor_sync(0xffffffffu, mx0, 1));
        mx0 = fmaxf(mx0, __shfl_xor_sync(0xffffffffu, mx0, 2));
        mx1 = fmaxf(mx1, __shfl_xor_sync(0xffffffffu, mx1, 1));
        mx1 = fmaxf(mx1, __shfl_xor_sync(0xffffffffu, mx1, 2));
        const float mn0 = fmaxf(m0, mx0);
        const float mn1 = fmaxf(m1, mx1);
        const float al0 = __expf(m0 - mn0);
        const float al1 = __expf(m1 - mn1);
        float rs0 = 0.f, rs1 = 0.f;
        #pragma unroll
        for (int nt = 0; nt < 8; nt++) {
            float p0 = __expf(s[nt][0] - mn0);
            float p1 = __expf(s[nt][1] - mn0);
            float p2 = __expf(s[nt][2] - mn1);
            float p3 = __expf(s[nt][3] - mn1);
            rs0 += p0 + p1;
            rs1 += p2 + p3;
            *(float2*)&Ps[rl * PST + nt * 8 + 2 * qd] =
                make_float2(to_tf32(p0), to_tf32(p1));
            *(float2*)&Ps[(rl + 8) * PST + nt * 8 + 2 * qd] =
                make_float2(to_tf32(p2), to_tf32(p3));
        }
        rs0 += __shfl_xor_sync(0xffffffffu, rs0, 1);
        rs0 += __shfl_xor_sync(0xffffffffu, rs0, 2);
        rs1 += __shfl_xor_sync(0xffffffffu, rs1, 1);
        rs1 += __shfl_xor_sync(0xffffffffu, rs1, 2);
        l0 = l0 * al0 + rs0;
        l1 = l1 * al1 + rs1;
        m0 = mn0;
        m1 = mn1;
        #pragma unroll
        for (int nt = 0; nt < 8; nt++) {
            o[nt][0] *= al0; o[nt][1] *= al0;
            o[nt][2] *= al1; o[nt][3] *= al1;
        }
        __syncwarp();   // P rows are warp-private

        // ---- O += P V (fragment-major LDS64, no cvt) --------------------
        #pragma unroll
        for (int kt = 0; kt < 8; kt++) {
            float a[4];
            a[0] = Ps[rl * PST + kt * 8 + qd];
            a[1] = Ps[(rl + 8) * PST + kt * 8 + qd];
            a[2] = Ps[rl * PST + kt * 8 + qd + 4];
            a[3] = Ps[(rl + 8) * PST + kt * 8 + qd + 4];
            #pragma unroll
            for (int nt = 0; nt < 8; nt++) {
                float2 bv = *(float2*)&Vc[(kt * 8 + nt) * 64 + lane * 2];
                mma_tf32(o[nt], a, &bv.x);
            }
        }
        __syncthreads();                    // KF/VF reads done -> buf free
        if (it + 2 < 32) { cp_tile(it + 2, buf); cp_commit(); }
    }

    // ---- normalize + write ----------------------------------------------
    const float inv0 = 1.f / l0;
    const float inv1 = 1.f / l1;
    #pragma unroll
    for (int nt = 0; nt < 8; nt++) {
        const int col = h * DH_ + nt * 8 + 2 * qd;
        *(float2*)&out[((size_t)b * S_ + q0 + rl) * D_ + col] =
            make_float2(o[nt][0] * inv0, o[nt][1] * inv0);
        *(float2*)&out[((size_t)b * S_ + q0 + rl + 8) * D_ + col] =
            make_float2(o[nt][2] * inv1, o[nt][3] * inv1);
    }
}

// ---------------------------------------------------------------------------
extern "C" void kernel_launch(void* const* d_in, const int* in_sizes, int n_in,
                              void* d_out, int out_size)
{
    const float* q    = (const float*)d_in[0];
    const float* k    = (const float*)d_in[1];
    const float* v    = (const float*)d_in[2];
    const int*   mask = (const int*)  d_in[3];
    const float* Wq   = (const float*)d_in[4];
    const float* bq   = (const float*)d_in[5];
    const float* Wk   = (const float*)d_in[6];
    const float* bk   = (const float*)d_in[7];
    const float* Wv   = (const float*)d_in[8];
    const float* bv   = (const float*)d_in[9];
    float* out = (float*)d_out;

    (void)in_sizes; (void)n_in; (void)out_size;

    cudaFuncSetAttribute(proj_mma,
                         cudaFuncAttributeMaxDynamicSharedMemorySize, PSMEM_TOT);
    dim3 g1(D_/128, M_/128, 3);
    proj_mma<<<g1, 256, PSMEM_TOT>>>(q, k, v, Wq, Wk, Wv, bq, bk, bv);

    cudaFuncSetAttribute(flash_attn_mma,
                         cudaFuncAttributeMaxDynamicSharedMemorySize, FA_BYTES);
    dim3 g2(S_/128, B_*H_);
    flash_attn_mma<<<g2, 256, FA_BYTES>>>(mask, out);
}

// round 14
// speedup vs baseline: 2.1485x; 2.0061x over previous
#include <cuda_runtime.h>
#include <cuda_fp16.h>
#include <cstdint>

#define B_  2
#define S_  2048
#define D_  1024
#define H_  16
#define DH_ 64
#define M_  (B_*S_)

// fp16 copies of inputs/weights, and projected Q/K/V (allocation-free rule).
// __align__(256): cp.async needs 16B-aligned sources; half arrays default .align 2.
__device__ __align__(256) __half g_qh[M_*D_], g_kh[M_*D_], g_vh[M_*D_];
__device__ __align__(256) __half g_Wqh[D_*D_], g_Wkh[D_*D_], g_Wvh[D_*D_];
__device__ __align__(256) __half g_Q[M_*D_], g_K[M_*D_], g_V[M_*D_];

// ---------------------------------------------------------------------------
// Helpers (family-level PTX only: mma.sync sm_80, ldmatrix sm_75, cp.async)
// ---------------------------------------------------------------------------
__device__ __forceinline__ uint32_t smem_u32(const void* p){
    uint32_t a;
    asm("{ .reg .u64 t; cvta.to.shared.u64 t, %1; cvt.u32.u64 %0, t; }"
        : "=r"(a) : "l"(p));
    return a;
}
__device__ __forceinline__ void cp16(uint32_t dst, const void* src){
    asm volatile("cp.async.cg.shared.global [%0], [%1], 16;"
                 :: "r"(dst), "l"(src) : "memory");
}
__device__ __forceinline__ void cp_commit(){
    asm volatile("cp.async.commit_group;" ::: "memory");
}
__device__ __forceinline__ void cp_wait0(){
    asm volatile("cp.async.wait_group 0;" ::: "memory");
}
__device__ __forceinline__ void cp_wait1(){
    asm volatile("cp.async.wait_group 1;" ::: "memory");
}
__device__ __forceinline__ void cp_wait2(){
    asm volatile("cp.async.wait_group 2;" ::: "memory");
}
// m16n8k16 fp16 mma, fp32 accumulate
__device__ __forceinline__ void mma_f16(float* c, const uint32_t* a, const uint32_t* b){
    asm volatile(
        "mma.sync.aligned.m16n8k16.row.col.f32.f16.f16.f32 "
        "{%0,%1,%2,%3}, {%4,%5,%6,%7}, {%8,%9}, {%0,%1,%2,%3};"
        : "+f"(c[0]), "+f"(c[1]), "+f"(c[2]), "+f"(c[3])
        : "r"(a[0]), "r"(a[1]), "r"(a[2]), "r"(a[3]), "r"(b[0]), "r"(b[1]));
}
__device__ __forceinline__ void ldsm4(uint32_t& r0, uint32_t& r1,
                                      uint32_t& r2, uint32_t& r3, uint32_t a){
    asm volatile("ldmatrix.sync.aligned.m8n8.x4.shared.b16 {%0,%1,%2,%3}, [%4];"
                 : "=r"(r0), "=r"(r1), "=r"(r2), "=r"(r3) : "r"(a));
}
__device__ __forceinline__ void ldsm4t(uint32_t& r0, uint32_t& r1,
                                       uint32_t& r2, uint32_t& r3, uint32_t a){
    asm volatile("ldmatrix.sync.aligned.m8n8.x4.trans.shared.b16 {%0,%1,%2,%3}, [%4];"
                 : "=r"(r0), "=r"(r1), "=r"(r2), "=r"(r3) : "r"(a));
}

// ---------------------------------------------------------------------------
// fp32 -> fp16 pre-convert (memory bound)
// ---------------------------------------------------------------------------
__global__ void cvt_inputs(const float* __restrict__ q, const float* __restrict__ k,
                           const float* __restrict__ v){
    const float* s = (blockIdx.y == 0) ? q : (blockIdx.y == 1) ? k : v;
    __half* d = (blockIdx.y == 0) ? g_qh : (blockIdx.y == 1) ? g_kh : g_vh;
    int i = blockIdx.x * blockDim.x + threadIdx.x;      // n4 = M_*D_/4 exactly
    float4 x = ((const float4*)s)[i];
    ((__half2*)d)[2*i]   = __floats2half2_rn(x.x, x.y);
    ((__half2*)d)[2*i+1] = __floats2half2_rn(x.z, x.w);
}
__global__ void cvt_weights(const float* __restrict__ wq, const float* __restrict__ wk,
                            const float* __restrict__ wv){
    const float* s = (blockIdx.y == 0) ? wq : (blockIdx.y == 1) ? wk : wv;
    __half* d = (blockIdx.y == 0) ? g_Wqh : (blockIdx.y == 1) ? g_Wkh : g_Wvh;
    int i = blockIdx.x * blockDim.x + threadIdx.x;      // n4 = D_*D_/4 exactly
    float4 x = ((const float4*)s)[i];
    ((__half2*)d)[2*i]   = __floats2half2_rn(x.x, x.y);
    ((__half2*)d)[2*i+1] = __floats2half2_rn(x.z, x.w);
}

// ---------------------------------------------------------------------------
// Projection GEMM fp16 m16n8k16: C = A[4096,1024] @ W[1024,1024] + bias
// 128x128 tile, K-chunk 64, double-buffered cp.async, ldmatrix fragments.
// A smem stride 72 halfs (144B), B stride 136 halfs (272B): ldsm conflict-free.
// ---------------------------------------------------------------------------
#define ASTH 72
#define BSTH 136
#define PA_H (128*ASTH)              // 9216 halfs
#define PB_H (64*BSTH)               // 8704 halfs
#define PBUF_H (PA_H + PB_H)         // 17920 halfs
#define PSMEM_TOT (2*PBUF_H*2)       // 71680 bytes

__global__ __launch_bounds__(256, 2)
void proj_h(const float* __restrict__ bq, const float* __restrict__ bk,
            const float* __restrict__ bv)
{
    extern __shared__ __half smh[];
    const uint32_t smb = smem_u32(smh);
    const int tid = threadIdx.x, wid = tid >> 5, lane = tid & 31;
    const int wm = wid >> 2, wn = wid & 3, grp = lane >> 2, qd = lane & 3;

    const int z = blockIdx.z;
    const __half* A    = (z == 0) ? g_qh  : (z == 1) ? g_kh  : g_vh;
    const __half* W    = (z == 0) ? g_Wqh : (z == 1) ? g_Wkh : g_Wvh;
    const float*  bias = (z == 0) ? bq    : (z == 1) ? bk    : bv;
    __half* C          = (z == 0) ? g_Q   : (z == 1) ? g_K   : g_V;
    const int brow = blockIdx.y * 128, bcol = blockIdx.x * 128;

    auto cp_chunk = [&](int c, int buf){
        const int k0 = c * 64;
        const uint32_t Ab = smb + buf * (PBUF_H * 2);
        const uint32_t Bb = Ab + PA_H * 2;
        #pragma unroll
        for (int l = 0; l < 4; l++) {            // A: 128 rows x 64 halfs
            int idx = tid + l * 256;
            int row = idx >> 3, k8 = (idx & 7) * 8;
            cp16(Ab + (row * ASTH + k8) * 2,
                 &A[(size_t)(brow + row) * D_ + k0 + k8]);
        }
        #pragma unroll
        for (int l = 0; l < 4; l++) {            // B: 64 rows x 128 halfs
            int idx = tid + l * 256;
            int kk = idx >> 4, n8 = (idx & 15) * 8;
            cp16(Bb + (kk * BSTH + n8) * 2,
                 &W[(size_t)(k0 + kk) * D_ + bcol + n8]);
        }
    };

    float acc[4][4][4];
    #pragma unroll
    for (int i = 0; i < 4; i++)
        #pragma unroll
        for (int j = 0; j < 4; j++)
            #pragma unroll
            for (int r = 0; r < 4; r++) acc[i][j][r] = 0.f;

    // per-lane ldmatrix offsets (in halfs)
    const int a_loff = (lane & 15) * ASTH + (lane >> 4) * 8;
    const int b_loff = ((lane & 7) + ((lane >> 3) & 1) * 8) * BSTH
                     + ((lane >= 16) ? 8 : 0);

    cp_chunk(0, 0);
    cp_commit();
    cp_wait0();
    __syncthreads();

    for (int c = 0; c < 16; c++) {
        const int buf = c & 1;
        const uint32_t Ab = smb + buf * (PBUF_H * 2);
        const uint32_t Bb = Ab + PA_H * 2;

        if (c + 1 < 16) { cp_chunk(c + 1, buf ^ 1); cp_commit(); }

        #pragma unroll
        for (int kc = 0; kc < 4; kc++) {
            uint32_t a[4][4];
            #pragma unroll
            for (int i = 0; i < 4; i++)
                ldsm4(a[i][0], a[i][1], a[i][2], a[i][3],
                      Ab + ((wm * 64 + i * 16) * ASTH + kc * 16 + a_loff) * 2);
            uint32_t bfr[4][2];
            #pragma unroll
            for (int ntp = 0; ntp < 2; ntp++)
                ldsm4t(bfr[2*ntp][0], bfr[2*ntp][1],
                       bfr[2*ntp+1][0], bfr[2*ntp+1][1],
                       Bb + ((kc * 16) * BSTH + wn * 32 + ntp * 16 + b_loff) * 2);
            #pragma unroll
            for (int i = 0; i < 4; i++)
                #pragma unroll
                for (int j = 0; j < 4; j++)
                    mma_f16(acc[i][j], a[i], bfr[j]);
        }

        if (c + 1 < 16) cp_wait0();
        __syncthreads();
    }

    #pragma unroll
    for (int j = 0; j < 4; j++) {
        const int c0 = bcol + wn * 32 + j * 8 + 2 * qd;
        const float2 bb = *(const float2*)&bias[c0];
        #pragma unroll
        for (int i = 0; i < 4; i++) {
            const int r0 = brow + wm * 64 + i * 16 + grp;
            *(__half2*)&C[(size_t)r0 * D_ + c0] =
                __floats2half2_rn(acc[i][j][0] + bb.x, acc[i][j][1] + bb.y);
            *(__half2*)&C[(size_t)(r0 + 8) * D_ + c0] =
                __floats2half2_rn(acc[i][j][2] + bb.x, acc[i][j][3] + bb.y);
        }
    }
}

// ---------------------------------------------------------------------------
// Flash attention fp16 (FA2 style): 256 thr (8 warps x 16 q-rows), kv tile 64.
// Q fragments in registers (ldmatrix from one-shot smem stage).
// K/V fp16 cp.async double-buffered; fragments via ldmatrix (K non-trans,
// V trans). P stays in registers: S C-frag packs directly into PV A-frag.
// Strides 72 halfs (144B): ldsm conflict-free. 2 barriers/tile.
// ---------------------------------------------------------------------------
#define QSTH 72
#define KSTH 72
#define VSTH 72
#define OFF_Q 0
#define OFF_K (128*QSTH)                 // 9216 halfs
#define OFF_V (OFF_K + 2*64*KSTH)        // 18432
#define OFF_END (OFF_V + 2*64*VSTH)      // 27648 halfs
#define FA_BYTES (OFF_END*2 + 256)       // + madd floats

__global__ __launch_bounds__(256, 2)
void flash_attn_h(const int* __restrict__ mask, float* __restrict__ out)
{
    extern __shared__ __half smh[];
    float* madd = (float*)(smh + OFF_END);
    const uint32_t smb = smem_u32(smh);

    const int tid = threadIdx.x, w = tid >> 5, lane = tid & 31;
    const int grp = lane >> 2, qd = lane & 3;
    const int bh = blockIdx.y, b = bh >> 4, h = bh & 15;
    const int q0 = blockIdx.x * 128;
    const float scale = 0.03125f;        // 1/sqrt(1024)

    const __half* Qb = g_Q + (size_t)b * S_ * D_ + h * DH_;
    const __half* Kb = g_K + (size_t)b * S_ * D_ + h * DH_;
    const __half* Vb = g_V + (size_t)b * S_ * D_ + h * DH_;

    auto cp_tile = [&](int it, int buf){
        const int kv0 = it * 64;
        const uint32_t Kd = smb + (OFF_K + buf * 64 * KSTH) * 2;
        const uint32_t Vd = smb + (OFF_V + buf * 64 * VSTH) * 2;
        #pragma unroll
        for (int l = 0; l < 2; l++) {            // 64 rows x 64 halfs
            int idx = tid + l * 256;
            int row = idx >> 3, c8 = (idx & 7) * 8;
            cp16(Kd + (row * KSTH + c8) * 2, &Kb[(size_t)(kv0 + row) * D_ + c8]);
        }
        #pragma unroll
        for (int l = 0; l < 2; l++) {
            int idx = tid + l * 256;
            int row = idx >> 3, c8 = (idx & 7) * 8;
            cp16(Vd + (row * VSTH + c8) * 2, &Vb[(size_t)(kv0 + row) * D_ + c8]);
        }
    };

    // Stage Q tile (group 0): 128 rows x 64 halfs = 1024 x 16B chunks
    // (R13 bug: this loop ran l<2 and left rows 64-127 uninitialized -> NaN)
    #pragma unroll
    for (int l = 0; l < 4; l++) {
        int idx = tid + l * 256;                 // 0..1023
        int row = idx >> 3, c8 = (idx & 7) * 8;
        cp16(smb + (OFF_Q + row * QSTH + c8) * 2,
             &Qb[(size_t)(q0 + row) * D_ + c8]);
    }
    cp_commit();
    cp_tile(0, 0); cp_commit();
    cp_tile(1, 1); cp_commit();

    // per-lane ldmatrix offsets (halfs)
    const int a_loff = (lane & 15) * QSTH + (lane >> 4) * 8;
    const int k_loff = ((lane & 7) + ((lane >= 16) ? 8 : 0)) * KSTH
                     + ((lane >> 3) & 1) * 8;
    const int v_loff = ((lane & 7) + ((lane >> 3) & 1) * 8) * VSTH
                     + ((lane >= 16) ? 8 : 0);

    cp_wait2();                          // Q stage retired
    __syncthreads();
    uint32_t q[4][4];
    #pragma unroll
    for (int kc = 0; kc < 4; kc++)
        ldsm4(q[kc][0], q[kc][1], q[kc][2], q[kc][3],
              smb + ((w * 16) * QSTH + kc * 16 + a_loff) * 2);

    int mreg = 0;
    if (tid < 64) mreg = mask[b * S_ + tid];

    float o[8][4];
    #pragma unroll
    for (int nt = 0; nt < 8; nt++)
        #pragma unroll
        for (int r = 0; r < 4; r++) o[nt][r] = 0.f;
    float m0 = -1e30f, m1 = -1e30f, l0s = 0.f, l1s = 0.f;

    for (int it = 0; it < 32; it++) {
        const int buf = it & 1;
        if (it < 31) cp_wait1(); else cp_wait0();
        if (tid < 64) madd[tid] = mreg ? 0.f : -1e9f;
        __syncthreads();
        if (it + 1 < 32 && tid < 64)
            mreg = mask[b * S_ + (it + 1) * 64 + tid];

        const uint32_t Kcb = smb + (OFF_K + buf * 64 * KSTH) * 2;
        const uint32_t Vcb = smb + (OFF_V + buf * 64 * VSTH) * 2;

        // ---- S = Q K^T ---------------------------------------------------
        float s[8][4];
        #pragma unroll
        for (int nt = 0; nt < 8; nt++)
            #pragma unroll
            for (int r = 0; r < 4; r++) s[nt][r] = 0.f;

        #pragma unroll
        for (int kc = 0; kc < 4; kc++) {
            #pragma unroll
            for (int ntp = 0; ntp < 4; ntp++) {
                uint32_t r0, r1, r2, r3;
                ldsm4(r0, r1, r2, r3,
                      Kcb + ((ntp * 16) * KSTH + kc * 16 + k_loff) * 2);
                uint32_t bb0[2] = {r0, r1}, bb1[2] = {r2, r3};
                mma_f16(s[2*ntp],   q[kc], bb0);
                mma_f16(s[2*ntp+1], q[kc], bb1);
            }
        }

        // ---- online softmax; pack P directly into PV A-fragments --------
        float mx0 = -1e30f, mx1 = -1e30f;
        #pragma unroll
        for (int nt = 0; nt < 8; nt++) {
            float2 ma = *(float2*)&madd[nt * 8 + 2 * qd];
            s[nt][0] = fmaf(s[nt][0], scale, ma.x);
            s[nt][1] = fmaf(s[nt][1], scale, ma.y);
            s[nt][2] = fmaf(s[nt][2], scale, ma.x);
            s[nt][3] = fmaf(s[nt][3], scale, ma.y);
            mx0 = fmaxf(mx0, fmaxf(s[nt][0], s[nt][1]));
            mx1 = fmaxf(mx1, fmaxf(s[nt][2], s[nt][3]));
        }
        mx0 = fmaxf(mx0, __shfl_xor_sync(0xffffffffu, mx0, 1));
        mx0 = fmaxf(mx0, __shfl_xor_sync(0xffffffffu, mx0, 2));
        mx1 = fmaxf(mx1, __shfl_xor_sync(0xffffffffu, mx1, 1));
        mx1 = fmaxf(mx1, __shfl_xor_sync(0xffffffffu, mx1, 2));
        const float mn0 = fmaxf(m0, mx0);
        const float mn1 = fmaxf(m1, mx1);
        const float al0 = __expf(m0 - mn0);
        const float al1 = __expf(m1 - mn1);
        float rs0 = 0.f, rs1 = 0.f;
        uint32_t pa[4][4];
        #pragma unroll
        for (int nt = 0; nt < 8; nt++) {
            float p0 = __expf(s[nt][0] - mn0);
            float p1 = __expf(s[nt][1] - mn0);
            float p2 = __expf(s[nt][2] - mn1);
            float p3 = __expf(s[nt][3] - mn1);
            rs0 += p0 + p1;
            rs1 += p2 + p3;
            __half2 h01 = __floats2half2_rn(p0, p1);
            __half2 h23 = __floats2half2_rn(p2, p3);
            const int kc = nt >> 1, hi = (nt & 1) * 2;
            pa[kc][hi]     = *reinterpret_cast<uint32_t*>(&h01);
            pa[kc][hi + 1] = *reinterpret_cast<uint32_t*>(&h23);
        }
        rs0 += __shfl_xor_sync(0xffffffffu, rs0, 1);
        rs0 += __shfl_xor_sync(0xffffffffu, rs0, 2);
        rs1 += __shfl_xor_sync(0xffffffffu, rs1, 1);
        rs1 += __shfl_xor_sync(0xffffffffu, rs1, 2);
        l0s = l0s * al0 + rs0;
        l1s = l1s * al1 + rs1;
        m0 = mn0;
        m1 = mn1;
        #pragma unroll
        for (int nt = 0; nt < 8; nt++) {
            o[nt][0] *= al0; o[nt][1] *= al0;
            o[nt][2] *= al1; o[nt][3] *= al1;
        }

        // ---- O += P V ----------------------------------------------------
        #pragma unroll
        for (int kc = 0; kc < 4; kc++) {
            #pragma unroll
            for (int ntp = 0; ntp < 4; ntp++) {
                uint32_t r0, r1, r2, r3;
                ldsm4t(r0, r1, r2, r3,
                       Vcb + ((kc * 16) * VSTH + ntp * 16 + v_loff) * 2);
                uint32_t bb0[2] = {r0, r1}, bb1[2] = {r2, r3};
                mma_f16(o[2*ntp],   pa[kc], bb0);
                mma_f16(o[2*ntp+1], pa[kc], bb1);
            }
        }
        __syncthreads();                 // tile reads done -> buf reusable
        if (it + 2 < 32) { cp_tile(it + 2, buf); cp_commit(); }
    }

    // ---- normalize + write out[b, q, h*64+dh] ---------------------------
    const float inv0 = 1.f / l0s;
    const float inv1 = 1.f / l1s;
    const int rl = w * 16 + grp;
    #pragma unroll
    for (int nt = 0; nt < 8; nt++) {
        const int col = h * DH_ + nt * 8 + 2 * qd;
        *(float2*)&out[((size_t)b * S_ + q0 + rl) * D_ + col] =
            make_float2(o[nt][0] * inv0, o[nt][1] * inv0);
        *(float2*)&out[((size_t)b * S_ + q0 + rl + 8) * D_ + col] =
            make_float2(o[nt][2] * inv1, o[nt][3] * inv1);
    }
}

// ---------------------------------------------------------------------------
extern "C" void kernel_launch(void* const* d_in, const int* in_sizes, int n_in,
                              void* d_out, int out_size)
{
    const float* q    = (const float*)d_in[0];
    const float* k    = (const float*)d_in[1];
    const float* v    = (const float*)d_in[2];
    const int*   mask = (const int*)  d_in[3];
    const float* Wq   = (const float*)d_in[4];
    const float* bq   = (const float*)d_in[5];
    const float* Wk   = (const float*)d_in[6];
    const float* bk   = (const float*)d_in[7];
    const float* Wv   = (const float*)d_in[8];
    const float* bv   = (const float*)d_in[9];
    float* out = (float*)d_out;

    (void)in_sizes; (void)n_in; (void)out_size;

    cvt_inputs <<<dim3(M_*D_/4/256, 3), 256>>>(q, k, v);
    cvt_weights<<<dim3(D_*D_/4/256, 3), 256>>>(Wq, Wk, Wv);

    cudaFuncSetAttribute(proj_h,
                         cudaFuncAttributeMaxDynamicSharedMemorySize, PSMEM_TOT);
    dim3 g1(D_/128, M_/128, 3);
    proj_h<<<g1, 256, PSMEM_TOT>>>(bq, bk, bv);

    cudaFuncSetAttribute(flash_attn_h,
                         cudaFuncAttributeMaxDynamicSharedMemorySize, FA_BYTES);
    dim3 g2(S_/128, B_*H_);
    flash_attn_h<<<g2, 256, FA_BYTES>>>(mask, out);
}

// round 15
// speedup vs baseline: 2.2186x; 1.0326x over previous
#include <cuda_runtime.h>
#include <cuda_fp16.h>
#include <cstdint>

#define B_  2
#define S_  2048
#define D_  1024
#define H_  16
#define DH_ 64
#define M_  (B_*S_)

// fp16 copies of inputs/weights, and projected Q/K/V (allocation-free rule).
// __align__(256): cp.async needs 16B-aligned sources.
__device__ __align__(256) __half g_qh[M_*D_], g_kh[M_*D_], g_vh[M_*D_];
__device__ __align__(256) __half g_Wqh[D_*D_], g_Wkh[D_*D_], g_Wvh[D_*D_];
__device__ __align__(256) __half g_Q[M_*D_], g_K[M_*D_], g_V[M_*D_];

// ---------------------------------------------------------------------------
// Helpers (family-level PTX only: mma.sync sm_80, ldmatrix sm_75, cp.async)
// ---------------------------------------------------------------------------
__device__ __forceinline__ uint32_t smem_u32(const void* p){
    uint32_t a;
    asm("{ .reg .u64 t; cvta.to.shared.u64 t, %1; cvt.u32.u64 %0, t; }"
        : "=r"(a) : "l"(p));
    return a;
}
__device__ __forceinline__ void cp16(uint32_t dst, const void* src){
    asm volatile("cp.async.cg.shared.global [%0], [%1], 16;"
                 :: "r"(dst), "l"(src) : "memory");
}
__device__ __forceinline__ void cp_commit(){
    asm volatile("cp.async.commit_group;" ::: "memory");
}
__device__ __forceinline__ void cp_wait0(){
    asm volatile("cp.async.wait_group 0;" ::: "memory");
}
__device__ __forceinline__ void cp_wait1(){
    asm volatile("cp.async.wait_group 1;" ::: "memory");
}
__device__ __forceinline__ void cp_wait2(){
    asm volatile("cp.async.wait_group 2;" ::: "memory");
}
// m16n8k16 fp16 mma, fp32 accumulate
__device__ __forceinline__ void mma_f16(float* c, const uint32_t* a, const uint32_t* b){
    asm volatile(
        "mma.sync.aligned.m16n8k16.row.col.f32.f16.f16.f32 "
        "{%0,%1,%2,%3}, {%4,%5,%6,%7}, {%8,%9}, {%0,%1,%2,%3};"
        : "+f"(c[0]), "+f"(c[1]), "+f"(c[2]), "+f"(c[3])
        : "r"(a[0]), "r"(a[1]), "r"(a[2]), "r"(a[3]), "r"(b[0]), "r"(b[1]));
}
__device__ __forceinline__ void ldsm4(uint32_t& r0, uint32_t& r1,
                                      uint32_t& r2, uint32_t& r3, uint32_t a){
    asm volatile("ldmatrix.sync.aligned.m8n8.x4.shared.b16 {%0,%1,%2,%3}, [%4];"
                 : "=r"(r0), "=r"(r1), "=r"(r2), "=r"(r3) : "r"(a));
}
__device__ __forceinline__ void ldsm4t(uint32_t& r0, uint32_t& r1,
                                       uint32_t& r2, uint32_t& r3, uint32_t a){
    asm volatile("ldmatrix.sync.aligned.m8n8.x4.trans.shared.b16 {%0,%1,%2,%3}, [%4];"
                 : "=r"(r0), "=r"(r1), "=r"(r2), "=r"(r3) : "r"(a));
}

// ---------------------------------------------------------------------------
// fp32 -> fp16 pre-convert (memory bound)
// ---------------------------------------------------------------------------
__global__ void cvt_inputs(const float* __restrict__ q, const float* __restrict__ k,
                           const float* __restrict__ v){
    const float* s = (blockIdx.y == 0) ? q : (blockIdx.y == 1) ? k : v;
    __half* d = (blockIdx.y == 0) ? g_qh : (blockIdx.y == 1) ? g_kh : g_vh;
    int i = blockIdx.x * blockDim.x + threadIdx.x;
    float4 x = ((const float4*)s)[i];
    ((__half2*)d)[2*i]   = __floats2half2_rn(x.x, x.y);
    ((__half2*)d)[2*i+1] = __floats2half2_rn(x.z, x.w);
}
__global__ void cvt_weights(const float* __restrict__ wq, const float* __restrict__ wk,
                            const float* __restrict__ wv){
    const float* s = (blockIdx.y == 0) ? wq : (blockIdx.y == 1) ? wk : wv;
    __half* d = (blockIdx.y == 0) ? g_Wqh : (blockIdx.y == 1) ? g_Wkh : g_Wvh;
    int i = blockIdx.x * blockDim.x + threadIdx.x;
    float4 x = ((const float4*)s)[i];
    ((__half2*)d)[2*i]   = __floats2half2_rn(x.x, x.y);
    ((__half2*)d)[2*i+1] = __floats2half2_rn(x.z, x.w);
}

// ---------------------------------------------------------------------------
// Projection GEMM fp16 m16n8k16 (unchanged — passing since R14)
// ---------------------------------------------------------------------------
#define ASTH 72
#define BSTH 136
#define PA_H (128*ASTH)
#define PB_H (64*BSTH)
#define PBUF_H (PA_H + PB_H)
#define PSMEM_TOT (2*PBUF_H*2)

__global__ __launch_bounds__(256, 2)
void proj_h(const float* __restrict__ bq, const float* __restrict__ bk,
            const float* __restrict__ bv)
{
    extern __shared__ __half smh[];
    const uint32_t smb = smem_u32(smh);
    const int tid = threadIdx.x, wid = tid >> 5, lane = tid & 31;
    const int wm = wid >> 2, wn = wid & 3, grp = lane >> 2, qd = lane & 3;

    const int z = blockIdx.z;
    const __half* A    = (z == 0) ? g_qh  : (z == 1) ? g_kh  : g_vh;
    const __half* W    = (z == 0) ? g_Wqh : (z == 1) ? g_Wkh : g_Wvh;
    const float*  bias = (z == 0) ? bq    : (z == 1) ? bk    : bv;
    __half* C          = (z == 0) ? g_Q   : (z == 1) ? g_K   : g_V;
    const int brow = blockIdx.y * 128, bcol = blockIdx.x * 128;

    auto cp_chunk = [&](int c, int buf){
        const int k0 = c * 64;
        const uint32_t Ab = smb + buf * (PBUF_H * 2);
        const uint32_t Bb = Ab + PA_H * 2;
        #pragma unroll
        for (int l = 0; l < 4; l++) {
            int idx = tid + l * 256;
            int row = idx >> 3, k8 = (idx & 7) * 8;
            cp16(Ab + (row * ASTH + k8) * 2,
                 &A[(size_t)(brow + row) * D_ + k0 + k8]);
        }
        #pragma unroll
        for (int l = 0; l < 4; l++) {
            int idx = tid + l * 256;
            int kk = idx >> 4, n8 = (idx & 15) * 8;
            cp16(Bb + (kk * BSTH + n8) * 2,
                 &W[(size_t)(k0 + kk) * D_ + bcol + n8]);
        }
    };

    float acc[4][4][4];
    #pragma unroll
    for (int i = 0; i < 4; i++)
        #pragma unroll
        for (int j = 0; j < 4; j++)
            #pragma unroll
            for (int r = 0; r < 4; r++) acc[i][j][r] = 0.f;

    const int a_loff = (lane & 15) * ASTH + (lane >> 4) * 8;
    const int b_loff = ((lane & 7) + ((lane >> 3) & 1) * 8) * BSTH
                     + ((lane >= 16) ? 8 : 0);

    cp_chunk(0, 0);
    cp_commit();
    cp_wait0();
    __syncthreads();

    for (int c = 0; c < 16; c++) {
        const int buf = c & 1;
        const uint32_t Ab = smb + buf * (PBUF_H * 2);
        const uint32_t Bb = Ab + PA_H * 2;

        if (c + 1 < 16) { cp_chunk(c + 1, buf ^ 1); cp_commit(); }

        #pragma unroll
        for (int kc = 0; kc < 4; kc++) {
            uint32_t a[4][4];
            #pragma unroll
            for (int i = 0; i < 4; i++)
                ldsm4(a[i][0], a[i][1], a[i][2], a[i][3],
                      Ab + ((wm * 64 + i * 16) * ASTH + kc * 16 + a_loff) * 2);
            uint32_t bfr[4][2];
            #pragma unroll
            for (int ntp = 0; ntp < 2; ntp++)
                ldsm4t(bfr[2*ntp][0], bfr[2*ntp][1],
                       bfr[2*ntp+1][0], bfr[2*ntp+1][1],
                       Bb + ((kc * 16) * BSTH + wn * 32 + ntp * 16 + b_loff) * 2);
            #pragma unroll
            for (int i = 0; i < 4; i++)
                #pragma unroll
                for (int j = 0; j < 4; j++)
                    mma_f16(acc[i][j], a[i], bfr[j]);
        }

        if (c + 1 < 16) cp_wait0();
        __syncthreads();
    }

    #pragma unroll
    for (int j = 0; j < 4; j++) {
        const int c0 = bcol + wn * 32 + j * 8 + 2 * qd;
        const float2 bb = *(const float2*)&bias[c0];
        #pragma unroll
        for (int i = 0; i < 4; i++) {
            const int r0 = brow + wm * 64 + i * 16 + grp;
            *(__half2*)&C[(size_t)r0 * D_ + c0] =
                __floats2half2_rn(acc[i][j][0] + bb.x, acc[i][j][1] + bb.y);
            *(__half2*)&C[(size_t)(r0 + 8) * D_ + c0] =
                __floats2half2_rn(acc[i][j][2] + bb.x, acc[i][j][3] + bb.y);
        }
    }
}

// ---------------------------------------------------------------------------
// Flash attention fp16 v2: 256 thr (8 warps x 16 q-rows), kv tile 64.
// 3-stage K/V cp.async ring -> ONE barrier per tile. exp2-domain softmax.
// Deferred l-reduction (per-thread partials; cross-lane shfl once at end).
// madd double-buffered by tile parity (race-free under single barrier).
// ---------------------------------------------------------------------------
#define QSTH 72
#define KSTH 72
#define VSTH 72
#define OFF_Q 0
#define OFF_K (128*QSTH)                 // 9216 halfs
#define OFF_V (OFF_K + 3*64*KSTH)        // +13824
#define OFF_END (OFF_V + 3*64*VSTH)      // 36864 halfs
#define FA_BYTES (OFF_END*2 + 512)       // + madd[2][64] floats

__global__ __launch_bounds__(256, 2)
void flash_attn_h(const int* __restrict__ mask, float* __restrict__ out)
{
    extern __shared__ __half smh[];
    float* madd = (float*)(smh + OFF_END);   // [2][64]
    const uint32_t smb = smem_u32(smh);

    const int tid = threadIdx.x, w = tid >> 5, lane = tid & 31;
    const int grp = lane >> 2, qd = lane & 3;
    const int bh = blockIdx.y, b = bh >> 4, h = bh & 15;
    const int q0 = blockIdx.x * 128;
    const float SC = 0.03125f * 1.4426950408889634f;   // scale * log2(e)

    const __half* Qb = g_Q + (size_t)b * S_ * D_ + h * DH_;
    const __half* Kb = g_K + (size_t)b * S_ * D_ + h * DH_;
    const __half* Vb = g_V + (size_t)b * S_ * D_ + h * DH_;

    auto cp_tile = [&](int it, int buf){
        const int kv0 = it * 64;
        const uint32_t Kd = smb + (OFF_K + buf * 64 * KSTH) * 2;
        const uint32_t Vd = smb + (OFF_V + buf * 64 * VSTH) * 2;
        #pragma unroll
        for (int l = 0; l < 2; l++) {
            int idx = tid + l * 256;
            int row = idx >> 3, c8 = (idx & 7) * 8;
            cp16(Kd + (row * KSTH + c8) * 2, &Kb[(size_t)(kv0 + row) * D_ + c8]);
        }
        #pragma unroll
        for (int l = 0; l < 2; l++) {
            int idx = tid + l * 256;
            int row = idx >> 3, c8 = (idx & 7) * 8;
            cp16(Vd + (row * VSTH + c8) * 2, &Vb[(size_t)(kv0 + row) * D_ + c8]);
        }
    };

    // Stage Q tile (128 rows x 64 halfs = 1024 chunks), then prefetch kv 0,1
    #pragma unroll
    for (int l = 0; l < 4; l++) {
        int idx = tid + l * 256;
        int row = idx >> 3, c8 = (idx & 7) * 8;
        cp16(smb + (OFF_Q + row * QSTH + c8) * 2,
             &Qb[(size_t)(q0 + row) * D_ + c8]);
    }
    cp_commit();
    cp_tile(0, 0); cp_commit();
    cp_tile(1, 1); cp_commit();

    // per-lane ldmatrix offsets (halfs)
    const int a_loff = (lane & 15) * QSTH + (lane >> 4) * 8;
    const int k_loff = ((lane & 7) + ((lane >= 16) ? 8 : 0)) * KSTH
                     + ((lane >> 3) & 1) * 8;
    const int v_loff = ((lane & 7) + ((lane >> 3) & 1) * 8) * VSTH
                     + ((lane >= 16) ? 8 : 0);

    cp_wait2();                          // Q stage retired (kv 0,1 pending)
    __syncthreads();
    uint32_t q[4][4];
    #pragma unroll
    for (int kc = 0; kc < 4; kc++)
        ldsm4(q[kc][0], q[kc][1], q[kc][2], q[kc][3],
              smb + ((w * 16) * QSTH + kc * 16 + a_loff) * 2);

    int mreg = 0;
    if (tid < 64) mreg = mask[b * S_ + tid];

    float o[8][4];
    #pragma unroll
    for (int nt = 0; nt < 8; nt++)
        #pragma unroll
        for (int r = 0; r < 4; r++) o[nt][r] = 0.f;
    float m0 = -1e30f, m1 = -1e30f, l0s = 0.f, l1s = 0.f;

    int b3 = 0;                          // ring buffer index of tile `it`
    for (int it = 0; it < 32; it++) {
        if (it < 31) cp_wait1(); else cp_wait0();
        if (tid < 64) madd[(it & 1) * 64 + tid] = mreg ? 0.f : -1e9f;
        __syncthreads();                 // tile it + madd published; buf
                                         // (it+2)%3 free (read at it-1)
        if (it + 1 < 32 && tid < 64)
            mreg = mask[b * S_ + (it + 1) * 64 + tid];
        if (it + 2 < 32) {
            int bn = b3 + 2; if (bn >= 3) bn -= 3;
            cp_tile(it + 2, bn); cp_commit();
        }

        const uint32_t Kcb = smb + (OFF_K + b3 * 64 * KSTH) * 2;
        const uint32_t Vcb = smb + (OFF_V + b3 * 64 * VSTH) * 2;
        const float* mdd = madd + (it & 1) * 64;

        // ---- S = Q K^T ---------------------------------------------------
        float s[8][4];
        #pragma unroll
        for (int nt = 0; nt < 8; nt++)
            #pragma unroll
            for (int r = 0; r < 4; r++) s[nt][r] = 0.f;

        #pragma unroll
        for (int kc = 0; kc < 4; kc++) {
            #pragma unroll
            for (int ntp = 0; ntp < 4; ntp++) {
                uint32_t r0, r1, r2, r3;
                ldsm4(r0, r1, r2, r3,
                      Kcb + ((ntp * 16) * KSTH + kc * 16 + k_loff) * 2);
                uint32_t bb0[2] = {r0, r1}, bb1[2] = {r2, r3};
                mma_f16(s[2*ntp],   q[kc], bb0);
                mma_f16(s[2*ntp+1], q[kc], bb1);
            }
        }

        // ---- online softmax (log2 domain); P -> PV A-fragments ----------
        float mx0 = -1e30f, mx1 = -1e30f;
        #pragma unroll
        for (int nt = 0; nt < 8; nt++) {
            float2 ma = *(float2*)&mdd[nt * 8 + 2 * qd];
            s[nt][0] = fmaf(s[nt][0], SC, ma.x);
            s[nt][1] = fmaf(s[nt][1], SC, ma.y);
            s[nt][2] = fmaf(s[nt][2], SC, ma.x);
            s[nt][3] = fmaf(s[nt][3], SC, ma.y);
            mx0 = fmaxf(mx0, fmaxf(s[nt][0], s[nt][1]));
            mx1 = fmaxf(mx1, fmaxf(s[nt][2], s[nt][3]));
        }
        mx0 = fmaxf(mx0, __shfl_xor_sync(0xffffffffu, mx0, 1));
        mx0 = fmaxf(mx0, __shfl_xor_sync(0xffffffffu, mx0, 2));
        mx1 = fmaxf(mx1, __shfl_xor_sync(0xffffffffu, mx1, 1));
        mx1 = fmaxf(mx1, __shfl_xor_sync(0xffffffffu, mx1, 2));
        const float mn0 = fmaxf(m0, mx0);
        const float mn1 = fmaxf(m1, mx1);
        const float al0 = exp2f(m0 - mn0);
        const float al1 = exp2f(m1 - mn1);
        float rs0 = 0.f, rs1 = 0.f;
        uint32_t pa[4][4];
        #pragma unroll
        for (int nt = 0; nt < 8; nt++) {
            float p0 = exp2f(s[nt][0] - mn0);
            float p1 = exp2f(s[nt][1] - mn0);
            float p2 = exp2f(s[nt][2] - mn1);
            float p3 = exp2f(s[nt][3] - mn1);
            rs0 += p0 + p1;
            rs1 += p2 + p3;
            __half2 h01 = __floats2half2_rn(p0, p1);
            __half2 h23 = __floats2half2_rn(p2, p3);
            const int kc = nt >> 1, hi = (nt & 1) * 2;
            pa[kc][hi]     = *reinterpret_cast<uint32_t*>(&h01);
            pa[kc][hi + 1] = *reinterpret_cast<uint32_t*>(&h23);
        }
        // deferred l: per-thread partials only (shfl-reduce once at the end)
        l0s = l0s * al0 + rs0;
        l1s = l1s * al1 + rs1;
        m0 = mn0;
        m1 = mn1;
        #pragma unroll
        for (int nt = 0; nt < 8; nt++) {
            o[nt][0] *= al0; o[nt][1] *= al0;
            o[nt][2] *= al1; o[nt][3] *= al1;
        }

        // ---- O += P V ----------------------------------------------------
        #pragma unroll
        for (int kc = 0; kc < 4; kc++) {
            #pragma unroll
            for (int ntp = 0; ntp < 4; ntp++) {
                uint32_t r0, r1, r2, r3;
                ldsm4t(r0, r1, r2, r3,
                       Vcb + ((kc * 16) * VSTH + ntp * 16 + v_loff) * 2);
                uint32_t bb0[2] = {r0, r1}, bb1[2] = {r2, r3};
                mma_f16(o[2*ntp],   pa[kc], bb0);
                mma_f16(o[2*ntp+1], pa[kc], bb1);
            }
        }
        b3 = (b3 == 2) ? 0 : b3 + 1;
    }

    // ---- final cross-lane l reduce, normalize, write --------------------
    l0s += __shfl_xor_sync(0xffffffffu, l0s, 1);
    l0s += __shfl_xor_sync(0xffffffffu, l0s, 2);
    l1s += __shfl_xor_sync(0xffffffffu, l1s, 1);
    l1s += __shfl_xor_sync(0xffffffffu, l1s, 2);
    const float inv0 = 1.f / l0s;
    const float inv1 = 1.f / l1s;
    const int rl = w * 16 + grp;
    #pragma unroll
    for (int nt = 0; nt < 8; nt++) {
        const int col = h * DH_ + nt * 8 + 2 * qd;
        *(float2*)&out[((size_t)b * S_ + q0 + rl) * D_ + col] =
            make_float2(o[nt][0] * inv0, o[nt][1] * inv0);
        *(float2*)&out[((size_t)b * S_ + q0 + rl + 8) * D_ + col] =
            make_float2(o[nt][2] * inv1, o[nt][3] * inv1);
    }
}

// ---------------------------------------------------------------------------
extern "C" void kernel_launch(void* const* d_in, const int* in_sizes, int n_in,
                              void* d_out, int out_size)
{
    const float* q    = (const float*)d_in[0];
    const float* k    = (const float*)d_in[1];
    const float* v    = (const float*)d_in[2];
    const int*   mask = (const int*)  d_in[3];
    const float* Wq   = (const float*)d_in[4];
    const float* bq   = (const float*)d_in[5];
    const float* Wk   = (const float*)d_in[6];
    const float* bk   = (const float*)d_in[7];
    const float* Wv   = (const float*)d_in[8];
    const float* bv   = (const float*)d_in[9];
    float* out = (float*)d_out;

    (void)in_sizes; (void)n_in; (void)out_size;

    cvt_inputs <<<dim3(M_*D_/4/256, 3), 256>>>(q, k, v);
    cvt_weights<<<dim3(D_*D_/4/256, 3), 256>>>(Wq, Wk, Wv);

    cudaFuncSetAttribute(proj_h,
                         cudaFuncAttributeMaxDynamicSharedMemorySize, PSMEM_TOT);
    dim3 g1(D_/128, M_/128, 3);
    proj_h<<<g1, 256, PSMEM_TOT>>>(bq, bk, bv);

    cudaFuncSetAttribute(flash_attn_h,
                         cudaFuncAttributeMaxDynamicSharedMemorySize, FA_BYTES);
    dim3 g2(S_/128, B_*H_);
    flash_attn_h<<<g2, 256, FA_BYTES>>>(mask, out);
}